// round 8
// baseline (speedup 1.0000x reference)
#include <cuda_runtime.h>

#define NN 50000
#define NE 800000
#define HH 64

// Scratch (no runtime allocation allowed)
__device__ __align__(16) float g_u[NN * HH];      // h @ W1d^T
__device__ __align__(16) float g_p[NN * HH];      // nf @ W1a^T
__device__ __align__(16) float g_q[NN * HH];      // nf @ W1b^T

// CSR build scratch
__device__ int  g_cnt[NN];
__device__ int  g_off[NN + 1];
__device__ int  g_cur[NN];
__device__ __align__(16) int2 g_edge[NE];         // (src, edge_idx) sorted by dst

// Pre-transposed weights (filled by prep_kernel)
__device__ __align__(16) float g_WpqT[32 * 128];  // [k][j]: j<64 -> W1a, j>=64 -> W1b
__device__ __align__(16) float g_WuT[64 * 64];    // [k][j] = W1[j][80+k]
__device__ __align__(16) float g_W1cT[16 * 64];   // [k][j] = W1[j][64+k]
__device__ __align__(16) float g_W2T[64 * 64];    // [j][i] = W2[i][j]

__device__ __forceinline__ void fma4(float4& a, float x, const float4& wv) {
    a.x = fmaf(x, wv.x, a.x);
    a.y = fmaf(x, wv.y, a.y);
    a.z = fmaf(x, wv.z, a.z);
    a.w = fmaf(x, wv.w, a.w);
}

__device__ __forceinline__ void add4(float4& a, const float4& b) {
    a.x += b.x; a.y += b.y; a.z += b.z; a.w += b.w;
}

// ---------------------------------------------------------------------------
// Kernel 0: zero degree counters; block 0 transposes weights.
// ---------------------------------------------------------------------------
__global__ __launch_bounds__(256) void prep_kernel(
    const float* __restrict__ W1, const float* __restrict__ W2)
{
    int tid = blockIdx.x * blockDim.x + threadIdx.x;
    for (int i = tid; i < NN; i += gridDim.x * blockDim.x) g_cnt[i] = 0;

    if (blockIdx.x == 0) {
        for (int idx = threadIdx.x; idx < 64 * 144; idx += 256) {
            int j = idx / 144, k = idx % 144;
            float w = W1[idx];
            if (k < 32)       g_WpqT[k * 128 + j] = w;
            else if (k < 64)  g_WpqT[(k - 32) * 128 + 64 + j] = w;
            else if (k < 80)  g_W1cT[(k - 64) * 64 + j] = w;
            else              g_WuT[(k - 80) * 64 + j] = w;
        }
        for (int idx = threadIdx.x; idx < 64 * 64; idx += 256) {
            int i = idx >> 6, j = idx & 63;
            g_W2T[j * 64 + i] = W2[idx];
        }
    }
}

// ---------------------------------------------------------------------------
// CSR build: histogram of dst
// ---------------------------------------------------------------------------
__global__ __launch_bounds__(256) void hist_kernel(const int* __restrict__ dst, int E)
{
    int i = blockIdx.x * blockDim.x + threadIdx.x;
    if (i < E) atomicAdd(&g_cnt[__ldg(&dst[i])], 1);
}

// ---------------------------------------------------------------------------
// CSR build: single-block exclusive scan over g_cnt (49 elems/thread,
// sequential local sum -> block scan -> sequential write-out).
// ---------------------------------------------------------------------------
__global__ __launch_bounds__(1024) void scan_kernel(int E)
{
    __shared__ int s[1024];
    const int PER = (NN + 1023) / 1024;   // 49
    int tid = threadIdx.x;
    int base = tid * PER;

    int sum = 0;
    #pragma unroll 7
    for (int i = 0; i < PER; i++) {
        int idx = base + i;
        if (idx < NN) sum += g_cnt[idx];
    }
    s[tid] = sum;
    __syncthreads();
    #pragma unroll
    for (int d = 1; d < 1024; d <<= 1) {
        int t = (tid >= d) ? s[tid - d] : 0;
        __syncthreads();
        s[tid] += t;
        __syncthreads();
    }
    int run = s[tid] - sum;   // exclusive prefix of this thread's chunk
    #pragma unroll 7
    for (int i = 0; i < PER; i++) {
        int idx = base + i;
        if (idx < NN) {
            g_off[idx] = run;
            g_cur[idx] = run;
            run += g_cnt[idx];
        }
    }
    if (tid == 0) g_off[NN] = E;
}

// ---------------------------------------------------------------------------
// CSR build: scatter (src, edge_idx) into dst-sorted slots
// ---------------------------------------------------------------------------
__global__ __launch_bounds__(256) void scatter_kernel(
    const int* __restrict__ src, const int* __restrict__ dst, int E)
{
    int i = blockIdx.x * blockDim.x + threadIdx.x;
    if (i >= E) return;
    int d = __ldg(&dst[i]);
    int pos = atomicAdd(&g_cur[d], 1);
    g_edge[pos] = make_int2(__ldg(&src[i]), i);
}

// ---------------------------------------------------------------------------
// Kernel 1a: [p|q] = nf @ [W1a^T | W1b^T].  Tile: 64 nodes x 128 outputs, K=32.
// ---------------------------------------------------------------------------
__global__ __launch_bounds__(256) void pq_kernel(const float* __restrict__ nf, int N)
{
    __shared__ float sW[32 * 128];  // [k][j]
    __shared__ float sX[64 * 32];   // [node][k]

    for (int idx = threadIdx.x; idx < 32 * 128; idx += 256)
        sW[idx] = g_WpqT[idx];

    int n0 = blockIdx.x * 64;
    const float4* nf4 = reinterpret_cast<const float4*>(nf);
    float4* sX4 = reinterpret_cast<float4*>(sX);
    for (int idx = threadIdx.x; idx < 512; idx += 256) {
        int n = n0 + (idx >> 3);
        sX4[idx] = (n < N) ? __ldg(&nf4[n * 8 + (idx & 7)])
                           : make_float4(0.f, 0.f, 0.f, 0.f);
    }
    __syncthreads();

    int jg = threadIdx.x & 31;
    int ng = threadIdx.x >> 5;
    const float* xb = sX + ng * 8 * 32;
    const float4* sW4 = reinterpret_cast<const float4*>(sW);

    float4 acc[8];
    #pragma unroll
    for (int i = 0; i < 8; i++) acc[i] = make_float4(0.f, 0.f, 0.f, 0.f);

    #pragma unroll 8
    for (int k = 0; k < 32; k++) {
        float4 wv = sW4[k * 32 + jg];
        #pragma unroll
        for (int i = 0; i < 8; i++) fma4(acc[i], xb[i * 32 + k], wv);
    }

    float4* dst4 = (jg < 16) ? reinterpret_cast<float4*>(g_p)
                             : reinterpret_cast<float4*>(g_q);
    int jj = jg & 15;
    #pragma unroll
    for (int i = 0; i < 8; i++) {
        int n = n0 + ng * 8 + i;
        if (n < N) dst4[n * 16 + jj] = acc[i];
    }
}

// ---------------------------------------------------------------------------
// Kernel 1b: u = h @ W1d^T.  Tile: 128 nodes x 64 outputs, K=64.
// ---------------------------------------------------------------------------
__global__ __launch_bounds__(256) void u_kernel(const float* __restrict__ h, int N)
{
    __shared__ float sW[64 * 64];   // [k][j]
    __shared__ float sX[128 * 64];  // [node][k]

    for (int idx = threadIdx.x; idx < 64 * 64; idx += 256)
        sW[idx] = g_WuT[idx];

    int n0 = blockIdx.x * 128;
    const float4* h4 = reinterpret_cast<const float4*>(h);
    float4* sX4 = reinterpret_cast<float4*>(sX);
    for (int idx = threadIdx.x; idx < 2048; idx += 256) {
        int n = n0 + (idx >> 4);
        sX4[idx] = (n < N) ? __ldg(&h4[n * 16 + (idx & 15)])
                           : make_float4(0.f, 0.f, 0.f, 0.f);
    }
    __syncthreads();

    int jg = threadIdx.x & 15;
    int ng = threadIdx.x >> 4;
    const float* xb = sX + ng * 8 * 64;
    const float4* sW4 = reinterpret_cast<const float4*>(sW);

    float4 acc[8];
    #pragma unroll
    for (int i = 0; i < 8; i++) acc[i] = make_float4(0.f, 0.f, 0.f, 0.f);

    #pragma unroll 8
    for (int k = 0; k < 64; k++) {
        float4 wv = sW4[k * 16 + jg];
        #pragma unroll
        for (int i = 0; i < 8; i++) fma4(acc[i], xb[i * 64 + k], wv);
    }

    float4* du4 = reinterpret_cast<float4*>(g_u);
    #pragma unroll
    for (int i = 0; i < 8; i++) {
        int n = n0 + ng * 8 + i;
        if (n < N) du4[n * 16 + jg] = acc[i];
    }
}

// ---------------------------------------------------------------------------
// Fused gather + finalize, 2-way edge-parallel lanes.
// Warp = 2 edge slots x 16 feature-float4 lanes. Each iteration: 2 edges via
// LDG.128 per lane (unroll 4 pairs = 8 edges in flight). shfl_xor(16) merges
// slots. Then y = sums + p + deg*q + W1c@ef_sum, relu, staged 4-node W2 GEMM.
// ---------------------------------------------------------------------------
__global__ __launch_bounds__(256) void gather_finalize_kernel(
    const float* __restrict__ h, const float* __restrict__ ef,
    float* __restrict__ out, int N)
{
    __shared__ float sW1cT[16 * 64];
    __shared__ float sW2T[64 * 64];
    __shared__ __align__(16) float sY[8][4 * 64];
    __shared__ float sEf[8][4 * 16];

    for (int idx = threadIdx.x; idx < 16 * 64; idx += 256) sW1cT[idx] = g_W1cT[idx];
    for (int idx = threadIdx.x; idx < 64 * 64; idx += 256) sW2T[idx]  = g_W2T[idx];
    __syncthreads();

    int lane = threadIdx.x & 31;
    int warp = threadIdx.x >> 5;
    int slot = lane >> 4;          // 0 or 1
    int f4   = lane & 15;          // float4 index within 64-float row
    int gw = (blockIdx.x * blockDim.x + threadIdx.x) >> 5;
    int nb = gw * 4;
    if (nb >= N) return;
    int cnt = min(4, N - nb);

    const float4* u4 = reinterpret_cast<const float4*>(g_u);
    float dgv[4];

    for (int m = 0; m < cnt; m++) {
        int n = nb + m;
        int off0 = __ldg(&g_off[n]);
        int off1 = __ldg(&g_off[n + 1]);
        dgv[m] = (float)(off1 - off0);

        float4 acc = make_float4(0.f, 0.f, 0.f, 0.f);
        float aef = 0.f;

        int i = off0;
        for (; i + 8 <= off1; i += 8) {
            int2 eA = g_edge[i     + slot];
            int2 eB = g_edge[i + 2 + slot];
            int2 eC = g_edge[i + 4 + slot];
            int2 eD = g_edge[i + 6 + slot];
            float4 vA = __ldg(&u4[eA.x * 16 + f4]);
            float4 vB = __ldg(&u4[eB.x * 16 + f4]);
            float4 vC = __ldg(&u4[eC.x * 16 + f4]);
            float4 vD = __ldg(&u4[eD.x * 16 + f4]);
            float fA = __ldg(&ef[eA.y * 16 + f4]);
            float fB = __ldg(&ef[eB.y * 16 + f4]);
            float fC = __ldg(&ef[eC.y * 16 + f4]);
            float fD = __ldg(&ef[eD.y * 16 + f4]);
            add4(acc, vA); add4(acc, vB); add4(acc, vC); add4(acc, vD);
            aef += fA + fB + fC + fD;
        }
        for (; i + 2 <= off1; i += 2) {
            int2 e = g_edge[i + slot];
            float4 v = __ldg(&u4[e.x * 16 + f4]);
            float f = __ldg(&ef[e.y * 16 + f4]);
            add4(acc, v);
            aef += f;
        }
        if (i < off1 && slot == 0) {   // odd remainder: slot-0 lanes only
            int2 e = g_edge[i];
            float4 v = __ldg(&u4[e.x * 16 + f4]);
            float f = __ldg(&ef[e.y * 16 + f4]);
            add4(acc, v);
            aef += f;
        }

        // merge slot 0 + slot 1
        acc.x += __shfl_xor_sync(0xffffffffu, acc.x, 16);
        acc.y += __shfl_xor_sync(0xffffffffu, acc.y, 16);
        acc.z += __shfl_xor_sync(0xffffffffu, acc.z, 16);
        acc.w += __shfl_xor_sync(0xffffffffu, acc.w, 16);
        aef   += __shfl_xor_sync(0xffffffffu, aef,   16);

        if (lane < 16) {
            reinterpret_cast<float4*>(&sY[warp][m * 64])[f4] = acc;
            sEf[warp][m * 16 + lane] = aef;
        }
        __syncwarp();

        float dg = dgv[m];
        float y0 = sY[warp][m * 64 + lane]
                 + g_p[n * 64 + lane]      + dg * g_q[n * 64 + lane];
        float y1 = sY[warp][m * 64 + lane + 32]
                 + g_p[n * 64 + lane + 32] + dg * g_q[n * 64 + lane + 32];

        #pragma unroll
        for (int k = 0; k < 16; k++) {
            float mk = sEf[warp][m * 16 + k];
            y0 = fmaf(mk, sW1cT[k * 64 + lane],      y0);
            y1 = fmaf(mk, sW1cT[k * 64 + lane + 32], y1);
        }
        // lane only touches its own two slots: safe to overwrite in place
        sY[warp][m * 64 + lane]      = fmaxf(y0, 0.f);
        sY[warp][m * 64 + lane + 32] = fmaxf(y1, 0.f);
    }
    __syncwarp();

    float o0[4] = {0.f, 0.f, 0.f, 0.f};
    float o1[4] = {0.f, 0.f, 0.f, 0.f};
    #pragma unroll
    for (int j = 0; j < 64; j++) {
        float w0 = sW2T[j * 64 + lane];
        float w1 = sW2T[j * 64 + lane + 32];
        #pragma unroll
        for (int m = 0; m < 4; m++) {
            float yj = sY[warp][m * 64 + j];
            o0[m] = fmaf(yj, w0, o0[m]);
            o1[m] = fmaf(yj, w1, o1[m]);
        }
    }

    for (int m = 0; m < cnt; m++) {
        int n = nb + m;
        if (dgv[m] > 0.f) {
            out[n * 64 + lane]      = o0[m];
            out[n * 64 + lane + 32] = o1[m];
        } else {
            out[n * 64 + lane]      = h[n * 64 + lane];
            out[n * 64 + lane + 32] = h[n * 64 + lane + 32];
        }
    }
}

// ---------------------------------------------------------------------------
extern "C" void kernel_launch(void* const* d_in, const int* in_sizes, int n_in,
                              void* d_out, int out_size)
{
    const float* h  = (const float*)d_in[0];
    const float* nf = (const float*)d_in[1];
    const float* ef = (const float*)d_in[2];
    const int*  src = (const int*)d_in[3];
    const int*  dst = (const int*)d_in[4];
    const float* W1 = (const float*)d_in[5];
    const float* W2 = (const float*)d_in[6];
    float* out = (float*)d_out;

    int N = in_sizes[1] / 32;   // nf is [N, 32]
    int E = in_sizes[3];        // src is [E]

    int ge   = (E + 255) / 256;
    int gpq  = (N + 63) / 64;
    int gu   = (N + 127) / 128;
    int gf   = (N + 31) / 32;

    prep_kernel<<<148, 256>>>(W1, W2);
    hist_kernel<<<ge, 256>>>(dst, E);
    scan_kernel<<<1, 1024>>>(E);
    scatter_kernel<<<ge, 256>>>(src, dst, E);
    pq_kernel<<<gpq, 256>>>(nf, N);
    u_kernel<<<gu, 256>>>(h, N);
    gather_finalize_kernel<<<gf, 256>>>(h, ef, out, N);
}

// round 9
// speedup vs baseline: 1.4324x; 1.4324x over previous
#include <cuda_runtime.h>

#define NN 50000
#define NE 800000
#define HH 64

// Scratch (no runtime allocation allowed)
__device__ __align__(16) float g_u[NN * HH];      // h @ W1d^T
__device__ __align__(16) float g_p[NN * HH];      // nf @ W1a^T
__device__ __align__(16) float g_q[NN * HH];      // nf @ W1b^T

// CSR build scratch
__device__ int  g_cnt[NN];
__device__ int  g_off[NN + 1];
__device__ int  g_cur[NN];
__device__ int  g_bsum[64];
__device__ __align__(16) int2 g_edge[NE];         // (src, edge_idx) sorted by dst

// Pre-transposed weights (filled by prep_kernel)
__device__ __align__(16) float g_WpqT[32 * 128];  // [k][j]: j<64 -> W1a, j>=64 -> W1b
__device__ __align__(16) float g_WuT[64 * 64];    // [k][j] = W1[j][80+k]
__device__ __align__(16) float g_W1cT[16 * 64];   // [k][j] = W1[j][64+k]
__device__ __align__(16) float g_W2T[64 * 64];    // [j][i] = W2[i][j]

__device__ __forceinline__ void fma4(float4& a, float x, const float4& wv) {
    a.x = fmaf(x, wv.x, a.x);
    a.y = fmaf(x, wv.y, a.y);
    a.z = fmaf(x, wv.z, a.z);
    a.w = fmaf(x, wv.w, a.w);
}

__device__ __forceinline__ void add4(float4& a, const float4& b) {
    a.x += b.x; a.y += b.y; a.z += b.z; a.w += b.w;
}

// ---------------------------------------------------------------------------
// Kernel 0: zero degree counters; block 0 transposes weights.
// ---------------------------------------------------------------------------
__global__ __launch_bounds__(256) void prep_kernel(
    const float* __restrict__ W1, const float* __restrict__ W2)
{
    int tid = blockIdx.x * blockDim.x + threadIdx.x;
    for (int i = tid; i < NN; i += gridDim.x * blockDim.x) g_cnt[i] = 0;

    if (blockIdx.x == 0) {
        for (int idx = threadIdx.x; idx < 64 * 144; idx += 256) {
            int j = idx / 144, k = idx % 144;
            float w = W1[idx];
            if (k < 32)       g_WpqT[k * 128 + j] = w;
            else if (k < 64)  g_WpqT[(k - 32) * 128 + 64 + j] = w;
            else if (k < 80)  g_W1cT[(k - 64) * 64 + j] = w;
            else              g_WuT[(k - 80) * 64 + j] = w;
        }
        for (int idx = threadIdx.x; idx < 64 * 64; idx += 256) {
            int i = idx >> 6, j = idx & 63;
            g_W2T[j * 64 + i] = W2[idx];
        }
    }
}

// ---------------------------------------------------------------------------
// CSR build: histogram of dst
// ---------------------------------------------------------------------------
__global__ __launch_bounds__(256) void hist_kernel(const int* __restrict__ dst, int E)
{
    int i = blockIdx.x * blockDim.x + threadIdx.x;
    if (i < E) atomicAdd(&g_cnt[__ldg(&dst[i])], 1);
}

// ---------------------------------------------------------------------------
// CSR build: per-1024-chunk exclusive scan (Hillis-Steele) + chunk totals.
// 49 blocks -> coalesced, spread across SMs.
// ---------------------------------------------------------------------------
__global__ __launch_bounds__(1024) void scan1_kernel()
{
    __shared__ int s[1024];
    int tid = threadIdx.x;
    int idx = blockIdx.x * 1024 + tid;
    int v = (idx < NN) ? g_cnt[idx] : 0;
    s[tid] = v;
    __syncthreads();
    #pragma unroll
    for (int d = 1; d < 1024; d <<= 1) {
        int t = (tid >= d) ? s[tid - d] : 0;
        __syncthreads();
        s[tid] += t;
        __syncthreads();
    }
    if (idx < NN) g_off[idx] = s[tid] - v;   // exclusive
    if (tid == 1023) g_bsum[blockIdx.x] = s[1023];
}

// ---------------------------------------------------------------------------
// CSR build: add chunk-prefix; copy to g_cur for the scatter pass
// ---------------------------------------------------------------------------
__global__ __launch_bounds__(1024) void scan2_kernel(int E)
{
    int b = blockIdx.x, tid = threadIdx.x;
    int idx = b * 1024 + tid;
    int add = 0;
    for (int j = 0; j < b; j++) add += g_bsum[j];   // uniform, tiny
    if (idx < NN) {
        int v = g_off[idx] + add;
        g_off[idx] = v;
        g_cur[idx] = v;
    }
    if (b == 0 && tid == 0) g_off[NN] = E;
}

// ---------------------------------------------------------------------------
// CSR build: scatter (src, edge_idx) into dst-sorted slots
// ---------------------------------------------------------------------------
__global__ __launch_bounds__(256) void scatter_kernel(
    const int* __restrict__ src, const int* __restrict__ dst, int E)
{
    int i = blockIdx.x * blockDim.x + threadIdx.x;
    if (i >= E) return;
    int d = __ldg(&dst[i]);
    int pos = atomicAdd(&g_cur[d], 1);
    g_edge[pos] = make_int2(__ldg(&src[i]), i);
}

// ---------------------------------------------------------------------------
// Kernel 1a: [p|q] = nf @ [W1a^T | W1b^T].  Tile: 64 nodes x 128 outputs, K=32.
// ---------------------------------------------------------------------------
__global__ __launch_bounds__(256) void pq_kernel(const float* __restrict__ nf, int N)
{
    __shared__ float sW[32 * 128];  // [k][j]
    __shared__ float sX[64 * 32];   // [node][k]

    for (int idx = threadIdx.x; idx < 32 * 128; idx += 256)
        sW[idx] = g_WpqT[idx];

    int n0 = blockIdx.x * 64;
    const float4* nf4 = reinterpret_cast<const float4*>(nf);
    float4* sX4 = reinterpret_cast<float4*>(sX);
    for (int idx = threadIdx.x; idx < 512; idx += 256) {
        int n = n0 + (idx >> 3);
        sX4[idx] = (n < N) ? __ldg(&nf4[n * 8 + (idx & 7)])
                           : make_float4(0.f, 0.f, 0.f, 0.f);
    }
    __syncthreads();

    int jg = threadIdx.x & 31;
    int ng = threadIdx.x >> 5;
    const float* xb = sX + ng * 8 * 32;
    const float4* sW4 = reinterpret_cast<const float4*>(sW);

    float4 acc[8];
    #pragma unroll
    for (int i = 0; i < 8; i++) acc[i] = make_float4(0.f, 0.f, 0.f, 0.f);

    #pragma unroll 8
    for (int k = 0; k < 32; k++) {
        float4 wv = sW4[k * 32 + jg];
        #pragma unroll
        for (int i = 0; i < 8; i++) fma4(acc[i], xb[i * 32 + k], wv);
    }

    float4* dst4 = (jg < 16) ? reinterpret_cast<float4*>(g_p)
                             : reinterpret_cast<float4*>(g_q);
    int jj = jg & 15;
    #pragma unroll
    for (int i = 0; i < 8; i++) {
        int n = n0 + ng * 8 + i;
        if (n < N) dst4[n * 16 + jj] = acc[i];
    }
}

// ---------------------------------------------------------------------------
// Kernel 1b: u = h @ W1d^T.  Tile: 128 nodes x 64 outputs, K=64.
// ---------------------------------------------------------------------------
__global__ __launch_bounds__(256) void u_kernel(const float* __restrict__ h, int N)
{
    __shared__ float sW[64 * 64];   // [k][j]
    __shared__ float sX[128 * 64];  // [node][k]

    for (int idx = threadIdx.x; idx < 64 * 64; idx += 256)
        sW[idx] = g_WuT[idx];

    int n0 = blockIdx.x * 128;
    const float4* h4 = reinterpret_cast<const float4*>(h);
    float4* sX4 = reinterpret_cast<float4*>(sX);
    for (int idx = threadIdx.x; idx < 2048; idx += 256) {
        int n = n0 + (idx >> 4);
        sX4[idx] = (n < N) ? __ldg(&h4[n * 16 + (idx & 15)])
                           : make_float4(0.f, 0.f, 0.f, 0.f);
    }
    __syncthreads();

    int jg = threadIdx.x & 15;
    int ng = threadIdx.x >> 4;
    const float* xb = sX + ng * 8 * 64;
    const float4* sW4 = reinterpret_cast<const float4*>(sW);

    float4 acc[8];
    #pragma unroll
    for (int i = 0; i < 8; i++) acc[i] = make_float4(0.f, 0.f, 0.f, 0.f);

    #pragma unroll 8
    for (int k = 0; k < 64; k++) {
        float4 wv = sW4[k * 16 + jg];
        #pragma unroll
        for (int i = 0; i < 8; i++) fma4(acc[i], xb[i * 64 + k], wv);
    }

    float4* du4 = reinterpret_cast<float4*>(g_u);
    #pragma unroll
    for (int i = 0; i < 8; i++) {
        int n = n0 + ng * 8 + i;
        if (n < N) du4[n * 16 + jg] = acc[i];
    }
}

// ---------------------------------------------------------------------------
// Fused gather + finalize, 2-way edge-parallel lanes.
// Warp = 2 edge slots x 16 feature-float4 lanes. Each iteration: 2 edges via
// LDG.128 per lane (unroll 4 pairs = 8 edges in flight). shfl_xor(16) merges
// slots. Then y = sums + p + deg*q + W1c@ef_sum, relu, staged 4-node W2 GEMM.
// ---------------------------------------------------------------------------
__global__ __launch_bounds__(256) void gather_finalize_kernel(
    const float* __restrict__ h, const float* __restrict__ ef,
    float* __restrict__ out, int N)
{
    __shared__ float sW1cT[16 * 64];
    __shared__ float sW2T[64 * 64];
    __shared__ __align__(16) float sY[8][4 * 64];
    __shared__ float sEf[8][4 * 16];

    for (int idx = threadIdx.x; idx < 16 * 64; idx += 256) sW1cT[idx] = g_W1cT[idx];
    for (int idx = threadIdx.x; idx < 64 * 64; idx += 256) sW2T[idx]  = g_W2T[idx];
    __syncthreads();

    int lane = threadIdx.x & 31;
    int warp = threadIdx.x >> 5;
    int slot = lane >> 4;          // 0 or 1
    int f4   = lane & 15;          // float4 index within 64-float row
    int gw = (blockIdx.x * blockDim.x + threadIdx.x) >> 5;
    int nb = gw * 4;
    if (nb >= N) return;
    int cnt = min(4, N - nb);

    const float4* u4 = reinterpret_cast<const float4*>(g_u);
    float dgv[4];

    for (int m = 0; m < cnt; m++) {
        int n = nb + m;
        int off0 = __ldg(&g_off[n]);
        int off1 = __ldg(&g_off[n + 1]);
        dgv[m] = (float)(off1 - off0);

        float4 acc = make_float4(0.f, 0.f, 0.f, 0.f);
        float aef = 0.f;

        int i = off0;
        for (; i + 8 <= off1; i += 8) {
            int2 eA = g_edge[i     + slot];
            int2 eB = g_edge[i + 2 + slot];
            int2 eC = g_edge[i + 4 + slot];
            int2 eD = g_edge[i + 6 + slot];
            float4 vA = __ldg(&u4[eA.x * 16 + f4]);
            float4 vB = __ldg(&u4[eB.x * 16 + f4]);
            float4 vC = __ldg(&u4[eC.x * 16 + f4]);
            float4 vD = __ldg(&u4[eD.x * 16 + f4]);
            float fA = __ldg(&ef[eA.y * 16 + f4]);
            float fB = __ldg(&ef[eB.y * 16 + f4]);
            float fC = __ldg(&ef[eC.y * 16 + f4]);
            float fD = __ldg(&ef[eD.y * 16 + f4]);
            add4(acc, vA); add4(acc, vB); add4(acc, vC); add4(acc, vD);
            aef += fA + fB + fC + fD;
        }
        for (; i + 2 <= off1; i += 2) {
            int2 e = g_edge[i + slot];
            float4 v = __ldg(&u4[e.x * 16 + f4]);
            float f = __ldg(&ef[e.y * 16 + f4]);
            add4(acc, v);
            aef += f;
        }
        if (i < off1 && slot == 0) {   // odd remainder: slot-0 lanes only
            int2 e = g_edge[i];
            float4 v = __ldg(&u4[e.x * 16 + f4]);
            float f = __ldg(&ef[e.y * 16 + f4]);
            add4(acc, v);
            aef += f;
        }

        // merge slot 0 + slot 1
        acc.x += __shfl_xor_sync(0xffffffffu, acc.x, 16);
        acc.y += __shfl_xor_sync(0xffffffffu, acc.y, 16);
        acc.z += __shfl_xor_sync(0xffffffffu, acc.z, 16);
        acc.w += __shfl_xor_sync(0xffffffffu, acc.w, 16);
        aef   += __shfl_xor_sync(0xffffffffu, aef,   16);

        if (lane < 16) {
            reinterpret_cast<float4*>(&sY[warp][m * 64])[f4] = acc;
            sEf[warp][m * 16 + lane] = aef;
        }
        __syncwarp();

        float dg = dgv[m];
        float y0 = sY[warp][m * 64 + lane]
                 + g_p[n * 64 + lane]      + dg * g_q[n * 64 + lane];
        float y1 = sY[warp][m * 64 + lane + 32]
                 + g_p[n * 64 + lane + 32] + dg * g_q[n * 64 + lane + 32];

        #pragma unroll
        for (int k = 0; k < 16; k++) {
            float mk = sEf[warp][m * 16 + k];
            y0 = fmaf(mk, sW1cT[k * 64 + lane],      y0);
            y1 = fmaf(mk, sW1cT[k * 64 + lane + 32], y1);
        }
        // lane only touches its own two slots: safe to overwrite in place
        sY[warp][m * 64 + lane]      = fmaxf(y0, 0.f);
        sY[warp][m * 64 + lane + 32] = fmaxf(y1, 0.f);
    }
    __syncwarp();

    float o0[4] = {0.f, 0.f, 0.f, 0.f};
    float o1[4] = {0.f, 0.f, 0.f, 0.f};
    #pragma unroll
    for (int j = 0; j < 64; j++) {
        float w0 = sW2T[j * 64 + lane];
        float w1 = sW2T[j * 64 + lane + 32];
        #pragma unroll
        for (int m = 0; m < 4; m++) {
            float yj = sY[warp][m * 64 + j];
            o0[m] = fmaf(yj, w0, o0[m]);
            o1[m] = fmaf(yj, w1, o1[m]);
        }
    }

    for (int m = 0; m < cnt; m++) {
        int n = nb + m;
        if (dgv[m] > 0.f) {
            out[n * 64 + lane]      = o0[m];
            out[n * 64 + lane + 32] = o1[m];
        } else {
            out[n * 64 + lane]      = h[n * 64 + lane];
            out[n * 64 + lane + 32] = h[n * 64 + lane + 32];
        }
    }
}

// ---------------------------------------------------------------------------
extern "C" void kernel_launch(void* const* d_in, const int* in_sizes, int n_in,
                              void* d_out, int out_size)
{
    const float* h  = (const float*)d_in[0];
    const float* nf = (const float*)d_in[1];
    const float* ef = (const float*)d_in[2];
    const int*  src = (const int*)d_in[3];
    const int*  dst = (const int*)d_in[4];
    const float* W1 = (const float*)d_in[5];
    const float* W2 = (const float*)d_in[6];
    float* out = (float*)d_out;

    int N = in_sizes[1] / 32;   // nf is [N, 32]
    int E = in_sizes[3];        // src is [E]

    int ge   = (E + 255) / 256;
    int gsc  = (NN + 1023) / 1024;   // 49
    int gpq  = (N + 63) / 64;
    int gu   = (N + 127) / 128;
    int gf   = (N + 31) / 32;

    prep_kernel<<<148, 256>>>(W1, W2);
    hist_kernel<<<ge, 256>>>(dst, E);
    scan1_kernel<<<gsc, 1024>>>();
    scan2_kernel<<<gsc, 1024>>>(E);
    scatter_kernel<<<ge, 256>>>(src, dst, E);
    pq_kernel<<<gpq, 256>>>(nf, N);
    u_kernel<<<gu, 256>>>(h, N);
    gather_finalize_kernel<<<gf, 256>>>(h, ef, out, N);
}

// round 10
// speedup vs baseline: 1.4512x; 1.0131x over previous
#include <cuda_runtime.h>

#define NN 50000
#define NE 800000
#define HH 64

// Scratch (no runtime allocation allowed)
__device__ __align__(16) float g_u[NN * HH];      // h @ W1d^T
__device__ __align__(16) float g_p[NN * HH];      // nf @ W1a^T
__device__ __align__(16) float g_q[NN * HH];      // nf @ W1b^T
__device__ __align__(16) float g_efs[NN * 16];    // per-dst ef sums (RED in scatter)

// CSR build scratch
__device__ int  g_cnt[NN];      // zero at load; re-zeroed by scan1 each run
__device__ int  g_off[NN + 1];
__device__ int  g_cur[NN];
__device__ int  g_bsum[64];
__device__ int  g_esrc[NE];     // src, sorted by dst

// Pre-transposed weights (filled by hist_kernel block 0)
__device__ __align__(16) float g_WpqT[32 * 128];  // [k][j]: j<64 -> W1a, j>=64 -> W1b
__device__ __align__(16) float g_WuT[64 * 64];    // [k][j] = W1[j][80+k]
__device__ __align__(16) float g_W1cT[16 * 64];   // [k][j] = W1[j][64+k]
__device__ __align__(16) float g_W2T[64 * 64];    // [j][i] = W2[i][j]

__device__ __forceinline__ void fma4(float4& a, float x, const float4& wv) {
    a.x = fmaf(x, wv.x, a.x);
    a.y = fmaf(x, wv.y, a.y);
    a.z = fmaf(x, wv.z, a.z);
    a.w = fmaf(x, wv.w, a.w);
}

__device__ __forceinline__ void add4(float4& a, const float4& b) {
    a.x += b.x; a.y += b.y; a.z += b.z; a.w += b.w;
}

// ---------------------------------------------------------------------------
// Launch 1: histogram of dst + zero g_efs; block 0 also transposes weights.
// Relies on g_cnt == 0 on entry (zero-init at load; scan1 re-zeroes each run).
// ---------------------------------------------------------------------------
__global__ __launch_bounds__(256) void hist_kernel(
    const int* __restrict__ dst, const float* __restrict__ W1,
    const float* __restrict__ W2, int E)
{
    int tid = blockIdx.x * blockDim.x + threadIdx.x;
    int stride = gridDim.x * blockDim.x;

    float4* efs4 = reinterpret_cast<float4*>(g_efs);
    float4 z = make_float4(0.f, 0.f, 0.f, 0.f);
    for (int i = tid; i < NN * 4; i += stride) efs4[i] = z;

    if (tid < E) atomicAdd(&g_cnt[__ldg(&dst[tid])], 1);

    if (blockIdx.x == 0) {
        for (int idx = threadIdx.x; idx < 64 * 144; idx += 256) {
            int j = idx / 144, k = idx % 144;
            float w = W1[idx];
            if (k < 32)       g_WpqT[k * 128 + j] = w;
            else if (k < 64)  g_WpqT[(k - 32) * 128 + 64 + j] = w;
            else if (k < 80)  g_W1cT[(k - 64) * 64 + j] = w;
            else              g_WuT[(k - 80) * 64 + j] = w;
        }
        for (int idx = threadIdx.x; idx < 64 * 64; idx += 256) {
            int i = idx >> 6, j = idx & 63;
            g_W2T[j * 64 + i] = W2[idx];
        }
    }
}

// ---------------------------------------------------------------------------
// Launch 2: per-1024-chunk exclusive scan + chunk totals; re-zero g_cnt.
// ---------------------------------------------------------------------------
__global__ __launch_bounds__(1024) void scan1_kernel()
{
    __shared__ int s[1024];
    int tid = threadIdx.x;
    int idx = blockIdx.x * 1024 + tid;
    int v = 0;
    if (idx < NN) {
        v = g_cnt[idx];
        g_cnt[idx] = 0;          // reset for next run (graph replay invariant)
    }
    s[tid] = v;
    __syncthreads();
    #pragma unroll
    for (int d = 1; d < 1024; d <<= 1) {
        int t = (tid >= d) ? s[tid - d] : 0;
        __syncthreads();
        s[tid] += t;
        __syncthreads();
    }
    if (idx < NN) g_off[idx] = s[tid] - v;   // exclusive (within chunk)
    if (tid == 1023) g_bsum[blockIdx.x] = s[1023];
}

// ---------------------------------------------------------------------------
// Launch 3 (block-partitioned fusion): scan2 | pq GEMM | u GEMM.
//   blocks [0,49):          finish scan (add chunk prefix, fill g_cur)
//   blocks [49,49+gpq):     [p|q] = nf @ [W1a^T|W1b^T]  (64 nodes x 128 out)
//   blocks [49+gpq,...):    u = h @ W1d^T               (128 nodes x 64 out)
// All three are mutually independent.
// ---------------------------------------------------------------------------
__global__ __launch_bounds__(256) void fused3_kernel(
    const float* __restrict__ nf, const float* __restrict__ h,
    int N, int E, int gpq)
{
    __shared__ __align__(16) char smem_raw[49152];
    int b = blockIdx.x;

    if (b < 49) {
        // ---- scan2: 1024 entries per block, 256 threads x 4 ----
        int add = 0;
        for (int j = 0; j < b; j++) add += g_bsum[j];   // uniform, tiny
        #pragma unroll
        for (int t = 0; t < 4; t++) {
            int idx = b * 1024 + t * 256 + threadIdx.x;
            if (idx < NN) {
                int v = g_off[idx] + add;
                g_off[idx] = v;
                g_cur[idx] = v;
            }
        }
        if (b == 0 && threadIdx.x == 0) g_off[NN] = E;
        return;
    }

    if (b < 49 + gpq) {
        // ---- pq GEMM ----
        int bid = b - 49;
        float* sW = reinterpret_cast<float*>(smem_raw);            // 32*128
        float* sX = reinterpret_cast<float*>(smem_raw + 16384);    // 64*32

        for (int idx = threadIdx.x; idx < 32 * 128; idx += 256)
            sW[idx] = g_WpqT[idx];

        int n0 = bid * 64;
        const float4* nf4 = reinterpret_cast<const float4*>(nf);
        float4* sX4 = reinterpret_cast<float4*>(sX);
        for (int idx = threadIdx.x; idx < 512; idx += 256) {
            int n = n0 + (idx >> 3);
            sX4[idx] = (n < N) ? __ldg(&nf4[n * 8 + (idx & 7)])
                               : make_float4(0.f, 0.f, 0.f, 0.f);
        }
        __syncthreads();

        int jg = threadIdx.x & 31;
        int ng = threadIdx.x >> 5;
        const float* xb = sX + ng * 8 * 32;
        const float4* sW4 = reinterpret_cast<const float4*>(sW);

        float4 acc[8];
        #pragma unroll
        for (int i = 0; i < 8; i++) acc[i] = make_float4(0.f, 0.f, 0.f, 0.f);

        #pragma unroll 8
        for (int k = 0; k < 32; k++) {
            float4 wv = sW4[k * 32 + jg];
            #pragma unroll
            for (int i = 0; i < 8; i++) fma4(acc[i], xb[i * 32 + k], wv);
        }

        float4* dst4 = (jg < 16) ? reinterpret_cast<float4*>(g_p)
                                 : reinterpret_cast<float4*>(g_q);
        int jj = jg & 15;
        #pragma unroll
        for (int i = 0; i < 8; i++) {
            int n = n0 + ng * 8 + i;
            if (n < N) dst4[n * 16 + jj] = acc[i];
        }
        return;
    }

    // ---- u GEMM ----
    {
        int bid = b - 49 - gpq;
        float* sW = reinterpret_cast<float*>(smem_raw);            // 64*64
        float* sX = reinterpret_cast<float*>(smem_raw + 16384);    // 128*64

        for (int idx = threadIdx.x; idx < 64 * 64; idx += 256)
            sW[idx] = g_WuT[idx];

        int n0 = bid * 128;
        const float4* h4 = reinterpret_cast<const float4*>(h);
        float4* sX4 = reinterpret_cast<float4*>(sX);
        for (int idx = threadIdx.x; idx < 2048; idx += 256) {
            int n = n0 + (idx >> 4);
            sX4[idx] = (n < N) ? __ldg(&h4[n * 16 + (idx & 15)])
                               : make_float4(0.f, 0.f, 0.f, 0.f);
        }
        __syncthreads();

        int jg = threadIdx.x & 15;
        int ng = threadIdx.x >> 4;
        const float* xb = sX + ng * 8 * 64;
        const float4* sW4 = reinterpret_cast<const float4*>(sW);

        float4 acc[8];
        #pragma unroll
        for (int i = 0; i < 8; i++) acc[i] = make_float4(0.f, 0.f, 0.f, 0.f);

        #pragma unroll 8
        for (int k = 0; k < 64; k++) {
            float4 wv = sW4[k * 16 + jg];
            #pragma unroll
            for (int i = 0; i < 8; i++) fma4(acc[i], xb[i * 64 + k], wv);
        }

        float4* du4 = reinterpret_cast<float4*>(g_u);
        #pragma unroll
        for (int i = 0; i < 8; i++) {
            int n = n0 + ng * 8 + i;
            if (n < N) du4[n * 16 + jg] = acc[i];
        }
    }
}

// ---------------------------------------------------------------------------
// Launch 4: scatter src into dst-sorted slots + RED ef sums per dst.
// ef reads are coalesced (consecutive edges per warp).
// ---------------------------------------------------------------------------
__global__ __launch_bounds__(256) void scatter_kernel(
    const int* __restrict__ src, const int* __restrict__ dst,
    const float* __restrict__ ef, int E)
{
    int i = blockIdx.x * blockDim.x + threadIdx.x;
    if (i >= E) return;
    int d = __ldg(&dst[i]);
    int pos = atomicAdd(&g_cur[d], 1);
    g_esrc[pos] = __ldg(&src[i]);

    const float4* ef4 = reinterpret_cast<const float4*>(ef);
    float4* efs4 = reinterpret_cast<float4*>(g_efs);
    #pragma unroll
    for (int c = 0; c < 4; c++)
        atomicAdd(&efs4[d * 4 + c], __ldg(&ef4[i * 4 + c]));
}

// ---------------------------------------------------------------------------
// Launch 5: fused gather + finalize, 2-way edge-parallel lanes, pure-u loop.
// Warp = 2 edge slots x 16 float4 lanes; unroll 4 pairs (8 edges in flight).
// y = u_sum + p + deg*q + W1c@efs; relu; staged 4-node W2 GEMM.
// ---------------------------------------------------------------------------
__global__ __launch_bounds__(256) void gather_finalize_kernel(
    const float* __restrict__ h, float* __restrict__ out, int N)
{
    __shared__ float sW1cT[16 * 64];
    __shared__ float sW2T[64 * 64];
    __shared__ __align__(16) float sY[8][4 * 64];
    __shared__ float sEf[8][4 * 16];

    for (int idx = threadIdx.x; idx < 16 * 64; idx += 256) sW1cT[idx] = g_W1cT[idx];
    for (int idx = threadIdx.x; idx < 64 * 64; idx += 256) sW2T[idx]  = g_W2T[idx];
    __syncthreads();

    int lane = threadIdx.x & 31;
    int warp = threadIdx.x >> 5;
    int slot = lane >> 4;          // 0 or 1
    int f4   = lane & 15;          // float4 index within 64-float row
    int gw = (blockIdx.x * blockDim.x + threadIdx.x) >> 5;
    int nb = gw * 4;
    if (nb >= N) return;
    int cnt = min(4, N - nb);

    const float4* u4 = reinterpret_cast<const float4*>(g_u);
    float dgv[4];

    for (int m = 0; m < cnt; m++) {
        int n = nb + m;
        int off0 = __ldg(&g_off[n]);
        int off1 = __ldg(&g_off[n + 1]);
        dgv[m] = (float)(off1 - off0);

        float4 acc = make_float4(0.f, 0.f, 0.f, 0.f);

        int i = off0;
        for (; i + 8 <= off1; i += 8) {
            int sA = __ldg(&g_esrc[i     + slot]);
            int sB = __ldg(&g_esrc[i + 2 + slot]);
            int sC = __ldg(&g_esrc[i + 4 + slot]);
            int sD = __ldg(&g_esrc[i + 6 + slot]);
            float4 vA = __ldg(&u4[sA * 16 + f4]);
            float4 vB = __ldg(&u4[sB * 16 + f4]);
            float4 vC = __ldg(&u4[sC * 16 + f4]);
            float4 vD = __ldg(&u4[sD * 16 + f4]);
            add4(acc, vA); add4(acc, vB); add4(acc, vC); add4(acc, vD);
        }
        for (; i + 2 <= off1; i += 2) {
            int s = __ldg(&g_esrc[i + slot]);
            float4 v = __ldg(&u4[s * 16 + f4]);
            add4(acc, v);
        }
        if (i < off1 && slot == 0) {   // odd remainder: slot-0 lanes only
            int s = __ldg(&g_esrc[i]);
            float4 v = __ldg(&u4[s * 16 + f4]);
            add4(acc, v);
        }

        // merge slot 0 + slot 1
        acc.x += __shfl_xor_sync(0xffffffffu, acc.x, 16);
        acc.y += __shfl_xor_sync(0xffffffffu, acc.y, 16);
        acc.z += __shfl_xor_sync(0xffffffffu, acc.z, 16);
        acc.w += __shfl_xor_sync(0xffffffffu, acc.w, 16);

        if (lane < 16) {
            reinterpret_cast<float4*>(&sY[warp][m * 64])[f4] = acc;
            sEf[warp][m * 16 + lane] = __ldg(&g_efs[n * 16 + lane]);
        }
        __syncwarp();

        float dg = dgv[m];
        float y0 = sY[warp][m * 64 + lane]
                 + g_p[n * 64 + lane]      + dg * g_q[n * 64 + lane];
        float y1 = sY[warp][m * 64 + lane + 32]
                 + g_p[n * 64 + lane + 32] + dg * g_q[n * 64 + lane + 32];

        #pragma unroll
        for (int k = 0; k < 16; k++) {
            float mk = sEf[warp][m * 16 + k];
            y0 = fmaf(mk, sW1cT[k * 64 + lane],      y0);
            y1 = fmaf(mk, sW1cT[k * 64 + lane + 32], y1);
        }
        sY[warp][m * 64 + lane]      = fmaxf(y0, 0.f);
        sY[warp][m * 64 + lane + 32] = fmaxf(y1, 0.f);
    }
    __syncwarp();

    float o0[4] = {0.f, 0.f, 0.f, 0.f};
    float o1[4] = {0.f, 0.f, 0.f, 0.f};
    #pragma unroll
    for (int j = 0; j < 64; j++) {
        float w0 = sW2T[j * 64 + lane];
        float w1 = sW2T[j * 64 + lane + 32];
        #pragma unroll
        for (int m = 0; m < 4; m++) {
            float yj = sY[warp][m * 64 + j];
            o0[m] = fmaf(yj, w0, o0[m]);
            o1[m] = fmaf(yj, w1, o1[m]);
        }
    }

    for (int m = 0; m < cnt; m++) {
        int n = nb + m;
        if (dgv[m] > 0.f) {
            out[n * 64 + lane]      = o0[m];
            out[n * 64 + lane + 32] = o1[m];
        } else {
            out[n * 64 + lane]      = h[n * 64 + lane];
            out[n * 64 + lane + 32] = h[n * 64 + lane + 32];
        }
    }
}

// ---------------------------------------------------------------------------
extern "C" void kernel_launch(void* const* d_in, const int* in_sizes, int n_in,
                              void* d_out, int out_size)
{
    const float* h  = (const float*)d_in[0];
    const float* nf = (const float*)d_in[1];
    const float* ef = (const float*)d_in[2];
    const int*  src = (const int*)d_in[3];
    const int*  dst = (const int*)d_in[4];
    const float* W1 = (const float*)d_in[5];
    const float* W2 = (const float*)d_in[6];
    float* out = (float*)d_out;

    int N = in_sizes[1] / 32;   // nf is [N, 32]
    int E = in_sizes[3];        // src is [E]

    int ge   = (E + 255) / 256;
    int gsc  = (NN + 1023) / 1024;     // 49
    int gpq  = (N + 63) / 64;
    int gu   = (N + 127) / 128;
    int gf   = (N + 31) / 32;

    hist_kernel<<<ge, 256>>>(dst, W1, W2, E);
    scan1_kernel<<<gsc, 1024>>>();
    fused3_kernel<<<49 + gpq + gu, 256>>>(nf, h, N, E, gpq);
    scatter_kernel<<<ge, 256>>>(src, dst, ef, E);
    gather_finalize_kernel<<<gf, 256>>>(h, out, N);
}

// round 12
// speedup vs baseline: 1.4813x; 1.0208x over previous
#include <cuda_runtime.h>

#define NN 50000
#define NE 800000
#define HH 64

// Scratch (no runtime allocation allowed)
__device__ __align__(16) float g_u[NN * HH];      // h @ W1d^T
__device__ __align__(16) float g_p[NN * HH];      // nf @ W1a^T
__device__ __align__(16) float g_q[NN * HH];      // nf @ W1b^T
__device__ __align__(16) float g_efs[NN * 16];    // per-dst ef sums (RED in scatter)

// CSR build scratch
__device__ int  g_cnt[NN];      // zero at load; re-zeroed by scan1 each run
__device__ int  g_off[NN + 1];
__device__ int  g_cur[NN];
__device__ int  g_bsum[64];
__device__ int  g_esrc[NE];     // src, sorted by dst

// Pre-transposed weights (filled by hist_kernel block 0)
__device__ __align__(16) float g_WpqT[32 * 128];  // [k][j]: j<64 -> W1a, j>=64 -> W1b
__device__ __align__(16) float g_WuT[64 * 64];    // [k][j] = W1[j][80+k]
__device__ __align__(16) float g_W1cT[16 * 64];   // [k][j] = W1[j][64+k]
__device__ __align__(16) float g_W2T[64 * 64];    // [j][i] = W2[i][j]

__device__ __forceinline__ void fma4(float4& a, float x, const float4& wv) {
    a.x = fmaf(x, wv.x, a.x);
    a.y = fmaf(x, wv.y, a.y);
    a.z = fmaf(x, wv.z, a.z);
    a.w = fmaf(x, wv.w, a.w);
}

__device__ __forceinline__ void add4(float4& a, const float4& b) {
    a.x += b.x; a.y += b.y; a.z += b.z; a.w += b.w;
}

// ---------------------------------------------------------------------------
// Launch 1: histogram of dst + zero g_efs; block 0 also transposes weights.
// Relies on g_cnt == 0 on entry (zero-init at load; scan1 re-zeroes each run).
// ---------------------------------------------------------------------------
__global__ __launch_bounds__(256) void hist_kernel(
    const int* __restrict__ dst, const float* __restrict__ W1,
    const float* __restrict__ W2, int E)
{
    int tid = blockIdx.x * blockDim.x + threadIdx.x;
    int stride = gridDim.x * blockDim.x;

    float4* efs4 = reinterpret_cast<float4*>(g_efs);
    float4 z = make_float4(0.f, 0.f, 0.f, 0.f);
    for (int i = tid; i < NN * 4; i += stride) efs4[i] = z;

    if (tid < E) atomicAdd(&g_cnt[__ldg(&dst[tid])], 1);

    if (blockIdx.x == 0) {
        for (int idx = threadIdx.x; idx < 64 * 144; idx += 256) {
            int j = idx / 144, k = idx % 144;
            float w = W1[idx];
            if (k < 32)       g_WpqT[k * 128 + j] = w;
            else if (k < 64)  g_WpqT[(k - 32) * 128 + 64 + j] = w;
            else if (k < 80)  g_W1cT[(k - 64) * 64 + j] = w;
            else              g_WuT[(k - 80) * 64 + j] = w;
        }
        for (int idx = threadIdx.x; idx < 64 * 64; idx += 256) {
            int i = idx >> 6, j = idx & 63;
            g_W2T[j * 64 + i] = W2[idx];
        }
    }
}

// ---------------------------------------------------------------------------
// Launch 2: per-1024-chunk exclusive scan + chunk totals; re-zero g_cnt.
// ---------------------------------------------------------------------------
__global__ __launch_bounds__(1024) void scan1_kernel()
{
    __shared__ int s[1024];
    int tid = threadIdx.x;
    int idx = blockIdx.x * 1024 + tid;
    int v = 0;
    if (idx < NN) {
        v = g_cnt[idx];
        g_cnt[idx] = 0;          // reset for next run (graph replay invariant)
    }
    s[tid] = v;
    __syncthreads();
    #pragma unroll
    for (int d = 1; d < 1024; d <<= 1) {
        int t = (tid >= d) ? s[tid - d] : 0;
        __syncthreads();
        s[tid] += t;
        __syncthreads();
    }
    if (idx < NN) g_off[idx] = s[tid] - v;   // exclusive (within chunk)
    if (tid == 1023) g_bsum[blockIdx.x] = s[1023];
}

// ---------------------------------------------------------------------------
// Launch 3: add chunk-prefix; fill g_cur. (Must finish before any scatter.)
// ---------------------------------------------------------------------------
__global__ __launch_bounds__(1024) void scan2_kernel(int E)
{
    int b = blockIdx.x, tid = threadIdx.x;
    int idx = b * 1024 + tid;
    int add = 0;
    for (int j = 0; j < b; j++) add += g_bsum[j];   // uniform, tiny
    if (idx < NN) {
        int v = g_off[idx] + add;
        g_off[idx] = v;
        g_cur[idx] = v;
    }
    if (b == 0 && tid == 0) g_off[NN] = E;
}

// ---------------------------------------------------------------------------
// Launch 4 (block-partitioned fusion): scatter | pq GEMM | u GEMM.
//   blocks [0, gs):            scatter src + RED ef sums (L2/latency-bound)
//   blocks [gs, gs+gpq):       [p|q] = nf @ [W1a^T|W1b^T] (FMA-bound)
//   blocks [gs+gpq, ...):      u = h @ W1d^T, 64-node tile (FMA-bound)
// Mutually independent; disjoint pipes overlap. 32KB static smem (7 blk/SM).
// ---------------------------------------------------------------------------
__global__ __launch_bounds__(256) void fused4_kernel(
    const int* __restrict__ src, const int* __restrict__ dst,
    const float* __restrict__ ef,
    const float* __restrict__ nf, const float* __restrict__ h,
    int N, int E, int gs, int gpq)
{
    __shared__ __align__(16) char smem_raw[32768];
    int b = blockIdx.x;

    if (b < gs) {
        // ---- scatter ----
        int i = b * 256 + threadIdx.x;
        if (i >= E) return;
        int d = __ldg(&dst[i]);
        int pos = atomicAdd(&g_cur[d], 1);
        g_esrc[pos] = __ldg(&src[i]);

        const float4* ef4 = reinterpret_cast<const float4*>(ef);
        float4* efs4 = reinterpret_cast<float4*>(g_efs);
        #pragma unroll
        for (int c = 0; c < 4; c++)
            atomicAdd(&efs4[d * 4 + c], __ldg(&ef4[i * 4 + c]));
        return;
    }

    if (b < gs + gpq) {
        // ---- pq GEMM: 64 nodes x 128 outputs, K=32 ----
        int bid = b - gs;
        float* sW = reinterpret_cast<float*>(smem_raw);            // 32*128 = 16KB
        float* sX = reinterpret_cast<float*>(smem_raw + 16384);    // 64*32  = 8KB

        for (int idx = threadIdx.x; idx < 32 * 128; idx += 256)
            sW[idx] = g_WpqT[idx];

        int n0 = bid * 64;
        const float4* nf4 = reinterpret_cast<const float4*>(nf);
        float4* sX4 = reinterpret_cast<float4*>(sX);
        for (int idx = threadIdx.x; idx < 512; idx += 256) {
            int n = n0 + (idx >> 3);
            sX4[idx] = (n < N) ? __ldg(&nf4[n * 8 + (idx & 7)])
                               : make_float4(0.f, 0.f, 0.f, 0.f);
        }
        __syncthreads();

        int jg = threadIdx.x & 31;
        int ng = threadIdx.x >> 5;
        const float* xb = sX + ng * 8 * 32;
        const float4* sW4 = reinterpret_cast<const float4*>(sW);

        float4 acc[8];
        #pragma unroll
        for (int i = 0; i < 8; i++) acc[i] = make_float4(0.f, 0.f, 0.f, 0.f);

        #pragma unroll 8
        for (int k = 0; k < 32; k++) {
            float4 wv = sW4[k * 32 + jg];
            #pragma unroll
            for (int i = 0; i < 8; i++) fma4(acc[i], xb[i * 32 + k], wv);
        }

        float4* dst4 = (jg < 16) ? reinterpret_cast<float4*>(g_p)
                                 : reinterpret_cast<float4*>(g_q);
        int jj = jg & 15;
        #pragma unroll
        for (int i = 0; i < 8; i++) {
            int n = n0 + ng * 8 + i;
            if (n < N) dst4[n * 16 + jj] = acc[i];
        }
        return;
    }

    // ---- u GEMM: 64 nodes x 64 outputs, K=64 (32KB smem) ----
    {
        int bid = b - gs - gpq;
        float* sW = reinterpret_cast<float*>(smem_raw);            // 64*64 = 16KB
        float* sX = reinterpret_cast<float*>(smem_raw + 16384);    // 64*64 = 16KB

        for (int idx = threadIdx.x; idx < 64 * 64; idx += 256)
            sW[idx] = g_WuT[idx];

        int n0 = bid * 64;
        const float4* h4 = reinterpret_cast<const float4*>(h);
        float4* sX4 = reinterpret_cast<float4*>(sX);
        for (int idx = threadIdx.x; idx < 1024; idx += 256) {
            int n = n0 + (idx >> 4);
            sX4[idx] = (n < N) ? __ldg(&h4[n * 16 + (idx & 15)])
                               : make_float4(0.f, 0.f, 0.f, 0.f);
        }
        __syncthreads();

        int jg = threadIdx.x & 15;    // 4 outputs
        int ng = threadIdx.x >> 4;    // 16 groups x 4 nodes
        const float* xb = sX + ng * 4 * 64;
        const float4* sW4 = reinterpret_cast<const float4*>(sW);

        float4 acc[4];
        #pragma unroll
        for (int i = 0; i < 4; i++) acc[i] = make_float4(0.f, 0.f, 0.f, 0.f);

        #pragma unroll 8
        for (int k = 0; k < 64; k++) {
            float4 wv = sW4[k * 16 + jg];
            #pragma unroll
            for (int i = 0; i < 4; i++) fma4(acc[i], xb[i * 64 + k], wv);
        }

        float4* du4 = reinterpret_cast<float4*>(g_u);
        #pragma unroll
        for (int i = 0; i < 4; i++) {
            int n = n0 + ng * 4 + i;
            if (n < N) du4[n * 16 + jg] = acc[i];
        }
    }
}

// ---------------------------------------------------------------------------
// Launch 5: fused gather + finalize, 2-way edge-parallel lanes, pure-u loop.
// Warp = 2 edge slots x 16 float4 lanes; unroll 4 pairs (8 edges in flight).
// y = u_sum + p + deg*q + W1c@efs; relu; staged 4-node W2 GEMM.
// ---------------------------------------------------------------------------
__global__ __launch_bounds__(256) void gather_finalize_kernel(
    const float* __restrict__ h, float* __restrict__ out, int N)
{
    __shared__ float sW1cT[16 * 64];
    __shared__ float sW2T[64 * 64];
    __shared__ __align__(16) float sY[8][4 * 64];
    __shared__ float sEf[8][4 * 16];

    for (int idx = threadIdx.x; idx < 16 * 64; idx += 256) sW1cT[idx] = g_W1cT[idx];
    for (int idx = threadIdx.x; idx < 64 * 64; idx += 256) sW2T[idx]  = g_W2T[idx];
    __syncthreads();

    int lane = threadIdx.x & 31;
    int warp = threadIdx.x >> 5;
    int slot = lane >> 4;          // 0 or 1
    int f4   = lane & 15;          // float4 index within 64-float row
    int gw = (blockIdx.x * blockDim.x + threadIdx.x) >> 5;
    int nb = gw * 4;
    if (nb >= N) return;
    int cnt = min(4, N - nb);

    const float4* u4 = reinterpret_cast<const float4*>(g_u);
    float dgv[4];

    for (int m = 0; m < cnt; m++) {
        int n = nb + m;
        int off0 = __ldg(&g_off[n]);
        int off1 = __ldg(&g_off[n + 1]);
        dgv[m] = (float)(off1 - off0);

        float4 acc = make_float4(0.f, 0.f, 0.f, 0.f);

        int i = off0;
        for (; i + 8 <= off1; i += 8) {
            int sA = __ldg(&g_esrc[i     + slot]);
            int sB = __ldg(&g_esrc[i + 2 + slot]);
            int sC = __ldg(&g_esrc[i + 4 + slot]);
            int sD = __ldg(&g_esrc[i + 6 + slot]);
            float4 vA = __ldg(&u4[sA * 16 + f4]);
            float4 vB = __ldg(&u4[sB * 16 + f4]);
            float4 vC = __ldg(&u4[sC * 16 + f4]);
            float4 vD = __ldg(&u4[sD * 16 + f4]);
            add4(acc, vA); add4(acc, vB); add4(acc, vC); add4(acc, vD);
        }
        for (; i + 2 <= off1; i += 2) {
            int s = __ldg(&g_esrc[i + slot]);
            float4 v = __ldg(&u4[s * 16 + f4]);
            add4(acc, v);
        }
        if (i < off1 && slot == 0) {   // odd remainder: slot-0 lanes only
            int s = __ldg(&g_esrc[i]);
            float4 v = __ldg(&u4[s * 16 + f4]);
            add4(acc, v);
        }

        // merge slot 0 + slot 1
        acc.x += __shfl_xor_sync(0xffffffffu, acc.x, 16);
        acc.y += __shfl_xor_sync(0xffffffffu, acc.y, 16);
        acc.z += __shfl_xor_sync(0xffffffffu, acc.z, 16);
        acc.w += __shfl_xor_sync(0xffffffffu, acc.w, 16);

        if (lane < 16) {
            reinterpret_cast<float4*>(&sY[warp][m * 64])[f4] = acc;
            sEf[warp][m * 16 + lane] = __ldg(&g_efs[n * 16 + lane]);
        }
        __syncwarp();

        float dg = dgv[m];
        float y0 = sY[warp][m * 64 + lane]
                 + g_p[n * 64 + lane]      + dg * g_q[n * 64 + lane];
        float y1 = sY[warp][m * 64 + lane + 32]
                 + g_p[n * 64 + lane + 32] + dg * g_q[n * 64 + lane + 32];

        #pragma unroll
        for (int k = 0; k < 16; k++) {
            float mk = sEf[warp][m * 16 + k];
            y0 = fmaf(mk, sW1cT[k * 64 + lane],      y0);
            y1 = fmaf(mk, sW1cT[k * 64 + lane + 32], y1);
        }
        sY[warp][m * 64 + lane]      = fmaxf(y0, 0.f);
        sY[warp][m * 64 + lane + 32] = fmaxf(y1, 0.f);
    }
    __syncwarp();

    float o0[4] = {0.f, 0.f, 0.f, 0.f};
    float o1[4] = {0.f, 0.f, 0.f, 0.f};
    #pragma unroll
    for (int j = 0; j < 64; j++) {
        float w0 = sW2T[j * 64 + lane];
        float w1 = sW2T[j * 64 + lane + 32];
        #pragma unroll
        for (int m = 0; m < 4; m++) {
            float yj = sY[warp][m * 64 + j];
            o0[m] = fmaf(yj, w0, o0[m]);
            o1[m] = fmaf(yj, w1, o1[m]);
        }
    }

    for (int m = 0; m < cnt; m++) {
        int n = nb + m;
        if (dgv[m] > 0.f) {
            out[n * 64 + lane]      = o0[m];
            out[n * 64 + lane + 32] = o1[m];
        } else {
            out[n * 64 + lane]      = h[n * 64 + lane];
            out[n * 64 + lane + 32] = h[n * 64 + lane + 32];
        }
    }
}

// ---------------------------------------------------------------------------
extern "C" void kernel_launch(void* const* d_in, const int* in_sizes, int n_in,
                              void* d_out, int out_size)
{
    const float* h  = (const float*)d_in[0];
    const float* nf = (const float*)d_in[1];
    const float* ef = (const float*)d_in[2];
    const int*  src = (const int*)d_in[3];
    const int*  dst = (const int*)d_in[4];
    const float* W1 = (const float*)d_in[5];
    const float* W2 = (const float*)d_in[6];
    float* out = (float*)d_out;

    int N = in_sizes[1] / 32;   // nf is [N, 32]
    int E = in_sizes[3];        // src is [E]

    int ge   = (E + 255) / 256;        // scatter / hist blocks
    int gsc  = (NN + 1023) / 1024;     // 49
    int gpq  = (N + 63) / 64;
    int gu   = (N + 63) / 64;
    int gf   = (N + 31) / 32;

    hist_kernel<<<ge, 256>>>(dst, W1, W2, E);
    scan1_kernel<<<gsc, 1024>>>();
    scan2_kernel<<<gsc, 1024>>>(E);
    fused4_kernel<<<ge + gpq + gu, 256>>>(src, dst, ef, nf, h, N, E, ge, gpq);
    gather_finalize_kernel<<<gf, 256>>>(h, out, N);
}